// round 1
// baseline (speedup 1.0000x reference)
#include <cuda_runtime.h>
#include <math.h>
#include <stdint.h>

#define N_  10000
#define E_  20000
#define B_  400
#define ND_ 32
#define ED_ 16
#define D_  64
#define DD_ 4096   // D*D

// ---------------- scratch (device globals; no cudaMalloc allowed) ----------------
__device__ float g_h[N_ * D_];          // node hidden / out
__device__ float g_r[E_ * D_];          // edge MLP hidden
__device__ float g_ew[(size_t)E_ * DD_]; // edge-conditioned weights [E, D, D] (327MB)
__device__ float g_agg[N_ * D_];        // scatter accumulator
__device__ float g_cnt[N_];             // dst degree
__device__ int   g_src[E_], g_dst[E_], g_batch[N_];
__device__ int   g_flags[2];            // [0]=edge_index is int64, [1]=batch is int64
__device__ int   g_gcnt[B_];
__device__ int   g_ptr[B_ + 1];
__device__ float g_qstar[B_ * 2 * D_];
__device__ float g_hl[B_ * D_];
__device__ float g_cl[B_ * D_];
__device__ float g_e[N_];               // per-node attention logits / weights

__device__ __forceinline__ float sigm(float x) { return 1.f / (1.f + expf(-x)); }

// ---------------- dtype detection (int64 vs int32 delivered buffers) ----------------
__global__ void detect_kernel(const void* ei, const void* ba) {
    if (threadIdx.x != 0) return;
    // edge_index: 2*E logical elements. If int32, the int64 view has 2*E/2 = 20000
    // valid entries; sampling near index 19999 is safe either way.
    {
        const long long* p = (const long long*)ei;
        int ok = 1;
        for (int i = 0; i < 8; i++) {
            long long v = p[i];
            if (v < 0 || v >= N_) ok = 0;
        }
        for (int i = 0; i < 8; i++) {
            long long v = p[2 * E_ / 2 - 8 + i];   // index 19992..19999
            if (v < 0 || v >= N_) ok = 0;
        }
        g_flags[0] = ok;
    }
    // batch: N logical elements. int64 view valid to 4999 if int32.
    {
        const long long* p = (const long long*)ba;
        int ok = 1;
        for (int i = 0; i < 8; i++) {
            long long v = p[i];
            if (v < 0 || v >= B_) ok = 0;
        }
        for (int i = 0; i < 8; i++) {
            long long v = p[N_ / 2 - 8 + i];       // index 4992..4999
            if (v < 0 || v >= B_) ok = 0;
        }
        g_flags[1] = ok;
    }
}

__global__ void convert_edges_kernel(const void* ei) {
    int i = blockIdx.x * blockDim.x + threadIdx.x;
    if (i >= E_) return;
    if (g_flags[0]) {
        const long long* p = (const long long*)ei;
        g_src[i] = (int)p[i];
        g_dst[i] = (int)p[E_ + i];
    } else {
        const int* p = (const int*)ei;
        g_src[i] = p[i];
        g_dst[i] = p[E_ + i];
    }
}

__global__ void convert_batch_kernel(const void* ba) {
    int i = blockIdx.x * blockDim.x + threadIdx.x;
    if (i >= N_) return;
    if (g_flags[1]) {
        const long long* p = (const long long*)ba;
        g_batch[i] = (int)p[i];
    } else {
        const int* p = (const int*)ba;
        g_batch[i] = p[i];
    }
}

// ---------------- misc small kernels ----------------
__global__ void zero_f_kernel(float* p, int n) {
    int i = blockIdx.x * blockDim.x + threadIdx.x;
    if (i < n) p[i] = 0.f;
}
__global__ void zero_i_kernel(int* p, int n) {
    int i = blockIdx.x * blockDim.x + threadIdx.x;
    if (i < n) p[i] = 0;
}
__global__ void count_deg_kernel() {
    int i = blockIdx.x * blockDim.x + threadIdx.x;
    if (i < E_) atomicAdd(&g_cnt[g_dst[i]], 1.0f);
}
__global__ void count_batch_kernel() {
    int i = blockIdx.x * blockDim.x + threadIdx.x;
    if (i < N_) atomicAdd(&g_gcnt[g_batch[i]], 1);
}
__global__ void scan_ptr_kernel() {
    if (threadIdx.x != 0) return;
    int acc = 0;
    g_ptr[0] = 0;
    for (int b = 0; b < B_; b++) { acc += g_gcnt[b]; g_ptr[b + 1] = acc; }
}

// ---------------- input linear: g_h = relu(x @ W_in^T + b_in) ----------------
__global__ void in_linear_kernel(const float* __restrict__ x,
                                 const float* __restrict__ W,
                                 const float* __restrict__ b) {
    int i = blockIdx.x * blockDim.x + threadIdx.x;
    if (i >= N_ * D_) return;
    int n = i >> 6, f = i & 63;
    float acc = b[f];
    const float* xr = x + n * ND_;
    const float* wr = W + f * ND_;
#pragma unroll
    for (int k = 0; k < ND_; k++) acc += xr[k] * wr[k];
    g_h[i] = fmaxf(acc, 0.f);
}

// ---------------- edge hidden: g_r = relu(edge_attr @ W_e1^T + b_e1) ----------------
__global__ void edge_hidden_kernel(const float* __restrict__ ea,
                                   const float* __restrict__ W,
                                   const float* __restrict__ b) {
    int i = blockIdx.x * blockDim.x + threadIdx.x;
    if (i >= E_ * D_) return;
    int e = i >> 6, f = i & 63;
    float acc = b[f];
    const float* er = ea + e * ED_;
    const float* wr = W + f * ED_;
#pragma unroll
    for (int k = 0; k < ED_; k++) acc += er[k] * wr[k];
    g_r[i] = fmaxf(acc, 0.f);
}

// ---------------- ew GEMM: g_ew[E,4096] = g_r[E,64] @ W_e2^T[64,4096] + b_e2 ------
// 128x128x64 tile, 256 threads, 8x8 register micro-tile, single K slab.
#define GM 128
#define GN 128
#define GPAD 129
__global__ void ew_gemm_kernel(const float* __restrict__ W,   // [4096,64]
                               const float* __restrict__ bias) {
    extern __shared__ float sm[];
    float* As = sm;              // [64][129] k-major over rows(edges)
    float* Bs = sm + 64 * GPAD;  // [64][129] k-major over cols
    int e0 = blockIdx.y * GM;
    int c0 = blockIdx.x * GN;
    int tid = threadIdx.x;

    for (int idx = tid; idx < GM * 64; idx += 256) {
        int m = idx >> 6, k = idx & 63;
        int e = e0 + m;
        As[k * GPAD + m] = (e < E_) ? g_r[e * 64 + k] : 0.f;
    }
    for (int idx = tid; idx < GN * 64; idx += 256) {
        int n = idx >> 6, k = idx & 63;
        Bs[k * GPAD + n] = W[(c0 + n) * 64 + k];
    }
    __syncthreads();

    int tx = tid & 15, ty = tid >> 4;
    float acc[8][8];
#pragma unroll
    for (int i = 0; i < 8; i++)
#pragma unroll
        for (int j = 0; j < 8; j++) acc[i][j] = 0.f;

#pragma unroll 16
    for (int k = 0; k < 64; k++) {
        float a[8], b[8];
#pragma unroll
        for (int i = 0; i < 8; i++) a[i] = As[k * GPAD + ty * 8 + i];
#pragma unroll
        for (int j = 0; j < 8; j++) b[j] = Bs[k * GPAD + tx * 8 + j];
#pragma unroll
        for (int i = 0; i < 8; i++)
#pragma unroll
            for (int j = 0; j < 8; j++) acc[i][j] += a[i] * b[j];
    }

    float bb[8];
#pragma unroll
    for (int j = 0; j < 8; j++) bb[j] = bias[c0 + tx * 8 + j];
#pragma unroll
    for (int i = 0; i < 8; i++) {
        int e = e0 + ty * 8 + i;
        if (e >= E_) continue;
        float* dst = &g_ew[(size_t)e * DD_ + c0 + tx * 8];
        float4 v0 = make_float4(acc[i][0] + bb[0], acc[i][1] + bb[1],
                                acc[i][2] + bb[2], acc[i][3] + bb[3]);
        float4 v1 = make_float4(acc[i][4] + bb[4], acc[i][5] + bb[5],
                                acc[i][6] + bb[6], acc[i][7] + bb[7]);
        *(float4*)(dst) = v0;
        *(float4*)(dst + 4) = v1;
    }
}

// ---------------- message + scatter: agg[dst] += ew[e]^T h[src] ----------------
// 2 edges per 128-thread block; thread f computes msg[e,f].
__global__ void msg_kernel() {
    int sub = threadIdx.x >> 6;
    int f = threadIdx.x & 63;
    int e = blockIdx.x * 2 + sub;
    __shared__ float s[2][64];
    int valid = (e < E_);
    int srcn = 0, dstn = 0;
    if (valid) {
        srcn = g_src[e];
        dstn = g_dst[e];
        s[sub][f] = g_h[srcn * 64 + f];
    }
    __syncthreads();
    if (!valid) return;
    const float* w = &g_ew[(size_t)e * DD_ + f];
    const float* sv = s[sub];
    float acc = 0.f;
#pragma unroll
    for (int d = 0; d < 64; d++) acc += sv[d] * w[d * 64];
    atomicAdd(&g_agg[dstn * 64 + f], acc);
}

// ---------------- GRU update over node tiles of 16 ----------------
// m = relu(agg/max(cnt,1) + b_conv); gi = m@Wih^T+bih; gh = h@Whh^T+bhh; gates; h <- new
__global__ void __launch_bounds__(192) gru_kernel(const float* __restrict__ Wih,
                                                  const float* __restrict__ bih,
                                                  const float* __restrict__ Whh,
                                                  const float* __restrict__ bhh,
                                                  const float* __restrict__ bconv) {
    __shared__ float Msm[16][64];
    __shared__ float Hsm[16][64];
    __shared__ float GI[16][192];
    __shared__ float GH[16][192];
    int n0 = blockIdx.x * 16;
    int tid = threadIdx.x;     // 0..191

    for (int idx = tid; idx < 16 * 64; idx += 192) {
        int m = idx >> 6, k = idx & 63;
        int n = n0 + m;
        if (n < N_) {
            float c = fmaxf(g_cnt[n], 1.0f);
            Msm[m][k] = fmaxf(g_agg[n * 64 + k] / c + bconv[k], 0.f);
            Hsm[m][k] = g_h[n * 64 + k];
        } else {
            Msm[m][k] = 0.f;
            Hsm[m][k] = 0.f;
        }
    }
    __syncthreads();

    // weights row j in registers
    float wih[64], whh[64];
    const float* wi = Wih + tid * 64;
    const float* wh = Whh + tid * 64;
#pragma unroll
    for (int k = 0; k < 64; k++) { wih[k] = __ldg(&wi[k]); whh[k] = __ldg(&wh[k]); }
    float bi = bih[tid], bh = bhh[tid];

#pragma unroll 4
    for (int m = 0; m < 16; m++) {
        float ai = bi, ah = bh;
#pragma unroll
        for (int k = 0; k < 64; k++) {
            ai += Msm[m][k] * wih[k];
            ah += Hsm[m][k] * whh[k];
        }
        GI[m][tid] = ai;
        GH[m][tid] = ah;
    }
    __syncthreads();

    for (int idx = tid; idx < 16 * 64; idx += 192) {
        int m = idx >> 6, f = idx & 63;
        int n = n0 + m;
        if (n >= N_) continue;
        float r = sigm(GI[m][f] + GH[m][f]);
        float z = sigm(GI[m][64 + f] + GH[m][64 + f]);
        float nn = tanhf(GI[m][128 + f] + r * GH[m][128 + f]);
        float hnew = (1.f - z) * nn + z * Hsm[m][f];
        g_h[n * 64 + f] = hnew;
    }
}

// ---------------- Set2Set LSTM cell (8 graphs per 256-thread block) ----------------
__global__ void lstm_kernel(const float* __restrict__ Wih, const float* __restrict__ bih,
                            const float* __restrict__ Whh, const float* __restrict__ bhh) {
    __shared__ float qs[8][128];
    __shared__ float hs[8][64];
    __shared__ float gsm[8][256];
    int b0 = blockIdx.x * 8;
    int tid = threadIdx.x;   // 0..255

    for (int idx = tid; idx < 8 * 128; idx += 256) {
        int g = idx >> 7, k = idx & 127;
        int b = b0 + g;
        qs[g][k] = (b < B_) ? g_qstar[b * 128 + k] : 0.f;
    }
    for (int idx = tid; idx < 8 * 64; idx += 256) {
        int g = idx >> 6, k = idx & 63;
        int b = b0 + g;
        hs[g][k] = (b < B_) ? g_hl[b * 64 + k] : 0.f;
    }
    __syncthreads();

    int j = tid;
    float acc[8];
    float bsum = bih[j] + bhh[j];
#pragma unroll
    for (int g = 0; g < 8; g++) acc[g] = bsum;
    const float* wi = Wih + j * 128;
    const float* wh = Whh + j * 64;
#pragma unroll 4
    for (int k = 0; k < 128; k++) {
        float w = __ldg(&wi[k]);
#pragma unroll
        for (int g = 0; g < 8; g++) acc[g] += qs[g][k] * w;
    }
#pragma unroll 4
    for (int k = 0; k < 64; k++) {
        float w = __ldg(&wh[k]);
#pragma unroll
        for (int g = 0; g < 8; g++) acc[g] += hs[g][k] * w;
    }
#pragma unroll
    for (int g = 0; g < 8; g++) gsm[g][j] = acc[g];
    __syncthreads();

    for (int idx = tid; idx < 8 * 64; idx += 256) {
        int g = idx >> 6, f = idx & 63;
        int b = b0 + g;
        if (b >= B_) continue;
        float ig = sigm(gsm[g][f]);
        float fg = sigm(gsm[g][64 + f]);
        float gg = tanhf(gsm[g][128 + f]);
        float og = sigm(gsm[g][192 + f]);
        float c = fg * g_cl[b * 64 + f] + ig * gg;
        float h = og * tanhf(c);
        g_cl[b * 64 + f] = c;
        g_hl[b * 64 + f] = h;
    }
}

// ---------------- attention (segment softmax + weighted sum) per graph ----------------
__global__ void attn_kernel() {
    int b = blockIdx.x;
    int tid = threadIdx.x;   // 128 threads
    __shared__ float qv[64];
    __shared__ float red[128];
    if (tid < 64) qv[tid] = g_hl[b * 64 + tid];
    __syncthreads();

    int s = g_ptr[b], eend = g_ptr[b + 1];

    float lmax = -INFINITY;
    for (int n = s + tid; n < eend; n += 128) {
        const float4* hr = (const float4*)&g_h[n * 64];
        const float4* qq = (const float4*)qv;
        float d = 0.f;
#pragma unroll
        for (int k = 0; k < 16; k++) {
            float4 a = hr[k], c = qq[k];
            d += a.x * c.x + a.y * c.y + a.z * c.z + a.w * c.w;
        }
        g_e[n] = d;
        lmax = fmaxf(lmax, d);
    }
    red[tid] = lmax;
    __syncthreads();
    for (int o = 64; o > 0; o >>= 1) {
        if (tid < o) red[tid] = fmaxf(red[tid], red[tid + o]);
        __syncthreads();
    }
    float mmax = red[0];
    __syncthreads();

    float lsum = 0.f;
    for (int n = s + tid; n < eend; n += 128) {
        float a = expf(g_e[n] - mmax);
        g_e[n] = a;
        lsum += a;
    }
    red[tid] = lsum;
    __syncthreads();
    for (int o = 64; o > 0; o >>= 1) {
        if (tid < o) red[tid] += red[tid + o];
        __syncthreads();
    }
    float den = red[0];
    __syncthreads();

    if (tid < 64) {
        float accr = 0.f;
        for (int n = s; n < eend; n++) accr += g_e[n] * g_h[n * 64 + tid];
        float rv = (den > 0.f) ? accr / den : 0.f;
        g_qstar[b * 128 + tid] = qv[tid];
        g_qstar[b * 128 + 64 + tid] = rv;
    }
}

// ---------------- output head ----------------
__global__ void out_head_kernel(const float* __restrict__ Wo1, const float* __restrict__ bo1,
                                const float* __restrict__ Wo2, const float* __restrict__ bo2,
                                float* __restrict__ out) {
    int b = blockIdx.x;
    int j = threadIdx.x;   // 64
    __shared__ float qs[128];
    __shared__ float hr[64];
    qs[j] = g_qstar[b * 128 + j];
    qs[64 + j] = g_qstar[b * 128 + 64 + j];
    __syncthreads();
    float acc = bo1[j];
    const float* wr = Wo1 + j * 128;
#pragma unroll 4
    for (int k = 0; k < 128; k++) acc += qs[k] * wr[k];
    acc = fmaxf(acc, 0.f) * Wo2[j];
    hr[j] = acc;
    __syncthreads();
    for (int o = 32; o > 0; o >>= 1) {
        if (j < o) hr[j] += hr[j + o];
        __syncthreads();
    }
    if (j == 0) out[b] = hr[0] + bo2[0];
}

// ---------------- host launch ----------------
extern "C" void kernel_launch(void* const* d_in, const int* in_sizes, int n_in,
                              void* d_out, int out_size) {
    const float* x      = (const float*)d_in[0];
    const float* eattr  = (const float*)d_in[1];
    const float* W_in   = (const float*)d_in[2];
    const float* b_in   = (const float*)d_in[3];
    const float* W_e1   = (const float*)d_in[4];
    const float* b_e1   = (const float*)d_in[5];
    const float* W_e2   = (const float*)d_in[6];
    const float* b_e2   = (const float*)d_in[7];
    const float* b_conv = (const float*)d_in[8];
    const float* W_ih   = (const float*)d_in[9];
    const float* b_ih   = (const float*)d_in[10];
    const float* W_hh   = (const float*)d_in[11];
    const float* b_hh   = (const float*)d_in[12];
    const float* W_ih_l = (const float*)d_in[13];
    const float* b_ih_l = (const float*)d_in[14];
    const float* W_hh_l = (const float*)d_in[15];
    const float* b_hh_l = (const float*)d_in[16];
    const float* W_o1   = (const float*)d_in[17];
    const float* b_o1   = (const float*)d_in[18];
    const float* W_o2   = (const float*)d_in[19];
    const float* b_o2   = (const float*)d_in[20];
    const void*  eidx   = d_in[21];
    const void*  batch  = d_in[22];
    float* out = (float*)d_out;

    // resolve device-global addresses for zero kernels
    float *p_cnt, *p_agg, *p_qstar, *p_hl, *p_cl;
    int* p_gcnt;
    cudaGetSymbolAddress((void**)&p_cnt, g_cnt);
    cudaGetSymbolAddress((void**)&p_agg, g_agg);
    cudaGetSymbolAddress((void**)&p_qstar, g_qstar);
    cudaGetSymbolAddress((void**)&p_hl, g_hl);
    cudaGetSymbolAddress((void**)&p_cl, g_cl);
    cudaGetSymbolAddress((void**)&p_gcnt, g_gcnt);

    static bool smem_set = false;
    if (!smem_set) {
        cudaFuncSetAttribute(ew_gemm_kernel,
                             cudaFuncAttributeMaxDynamicSharedMemorySize,
                             2 * 64 * GPAD * (int)sizeof(float));
        smem_set = true;
    }

    // graph/indices preprocessing
    detect_kernel<<<1, 32>>>(eidx, batch);
    convert_edges_kernel<<<(E_ + 255) / 256, 256>>>(eidx);
    convert_batch_kernel<<<(N_ + 255) / 256, 256>>>(batch);
    zero_f_kernel<<<(N_ + 255) / 256, 256>>>(p_cnt, N_);
    zero_i_kernel<<<(B_ + 255) / 256, 256>>>(p_gcnt, B_);
    count_deg_kernel<<<(E_ + 255) / 256, 256>>>();
    count_batch_kernel<<<(N_ + 255) / 256, 256>>>();
    scan_ptr_kernel<<<1, 32>>>();

    // encoders
    in_linear_kernel<<<(N_ * D_ + 255) / 256, 256>>>(x, W_in, b_in);
    edge_hidden_kernel<<<(E_ * D_ + 255) / 256, 256>>>(eattr, W_e1, b_e1);

    // edge-conditioned weight tensor
    dim3 ggrid(DD_ / GN, (E_ + GM - 1) / GM);
    ew_gemm_kernel<<<ggrid, 256, 2 * 64 * GPAD * sizeof(float)>>>(W_e2, b_e2);

    // 3 message-passing + GRU iterations
    for (int it = 0; it < 3; it++) {
        zero_f_kernel<<<(N_ * D_ + 255) / 256, 256>>>(p_agg, N_ * D_);
        msg_kernel<<<(E_ + 1) / 2, 128>>>();
        gru_kernel<<<(N_ + 15) / 16, 192>>>(W_ih, b_ih, W_hh, b_hh, b_conv);
    }

    // Set2Set
    zero_f_kernel<<<(B_ * 128 + 255) / 256, 256>>>(p_qstar, B_ * 128);
    zero_f_kernel<<<(B_ * 64 + 255) / 256, 256>>>(p_hl, B_ * 64);
    zero_f_kernel<<<(B_ * 64 + 255) / 256, 256>>>(p_cl, B_ * 64);
    for (int it = 0; it < 3; it++) {
        lstm_kernel<<<(B_ + 7) / 8, 256>>>(W_ih_l, b_ih_l, W_hh_l, b_hh_l);
        attn_kernel<<<B_, 128>>>();
    }

    out_head_kernel<<<B_, 64>>>(W_o1, b_o1, W_o2, b_o2, out);
}

// round 4
// speedup vs baseline: 1.1940x; 1.1940x over previous
#include <cuda_runtime.h>
#include <cuda_bf16.h>
#include <math.h>
#include <stdint.h>

#define N_  10000
#define E_  20000
#define B_  400
#define ND_ 32
#define ED_ 16
#define D_  64
#define DD_ 4096   // D*D

// ---------------- scratch (device globals; no cudaMalloc allowed) ----------------
__device__ float g_h[N_ * D_];            // node hidden / out
__device__ float g_r[E_ * D_];            // edge MLP hidden
__device__ float g_ew[(size_t)E_ * DD_];  // edge-conditioned weights [E, D, D] (327MB)
__device__ float g_agg[3 * N_ * D_];      // scatter accumulators (one per iteration)
__device__ float g_cnt[N_];               // dst degree
__device__ int   g_src[E_], g_dst[E_], g_batch[N_];
__device__ int   g_flags[2];              // [0]=edge_index is int64, [1]=batch is int64
__device__ int   g_gcnt[B_];
__device__ int   g_ptr[B_ + 1];
__device__ float g_qstar[B_ * 2 * D_];
__device__ float g_hl[B_ * D_];
__device__ float g_cl[B_ * D_];
__device__ float g_e[N_];                 // per-node attention logits / weights

__device__ __forceinline__ float sigm(float x) { return 1.f / (1.f + expf(-x)); }

__device__ __forceinline__ uint32_t smem_u32(const void* p) {
    uint32_t a;
    asm("{ .reg .u64 t; cvta.to.shared.u64 t, %1; cvt.u32.u64 %0, t; }" : "=r"(a) : "l"(p));
    return a;
}

// ---------------- dtype detection (int64 vs int32 delivered buffers) ----------------
__global__ void detect_kernel(const void* ei, const void* ba) {
    if (threadIdx.x != 0) return;
    {
        const long long* p = (const long long*)ei;
        int ok = 1;
        for (int i = 0; i < 8; i++) { long long v = p[i]; if (v < 0 || v >= N_) ok = 0; }
        for (int i = 0; i < 8; i++) { long long v = p[2 * E_ / 2 - 8 + i]; if (v < 0 || v >= N_) ok = 0; }
        g_flags[0] = ok;
    }
    {
        const long long* p = (const long long*)ba;
        int ok = 1;
        for (int i = 0; i < 8; i++) { long long v = p[i]; if (v < 0 || v >= B_) ok = 0; }
        for (int i = 0; i < 8; i++) { long long v = p[N_ / 2 - 8 + i]; if (v < 0 || v >= B_) ok = 0; }
        g_flags[1] = ok;
    }
}

__global__ void convert_kernel(const void* ei, const void* ba) {
    int i = blockIdx.x * blockDim.x + threadIdx.x;
    if (i < E_) {
        if (g_flags[0]) {
            const long long* p = (const long long*)ei;
            g_src[i] = (int)p[i];
            g_dst[i] = (int)p[E_ + i];
        } else {
            const int* p = (const int*)ei;
            g_src[i] = p[i];
            g_dst[i] = p[E_ + i];
        }
    }
    if (i < N_) {
        if (g_flags[1]) {
            const long long* p = (const long long*)ba;
            g_batch[i] = (int)p[i];
        } else {
            const int* p = (const int*)ba;
            g_batch[i] = p[i];
        }
    }
}

// ---------------- fused zero init (all accumulators, whole launch) ----------------
__global__ void init_zero_kernel() {
    int i = blockIdx.x * blockDim.x + threadIdx.x;
    int stride = gridDim.x * blockDim.x;
    for (int j = i; j < 3 * N_ * D_; j += stride) g_agg[j] = 0.f;
    if (i < N_) g_cnt[i] = 0.f;
    if (i < B_) g_gcnt[i] = 0;
    if (i < B_ * 2 * D_) g_qstar[i] = 0.f;
    if (i < B_ * D_) { g_hl[i] = 0.f; g_cl[i] = 0.f; }
}

__global__ void counts_kernel() {
    int i = blockIdx.x * blockDim.x + threadIdx.x;
    if (i < E_) atomicAdd(&g_cnt[g_dst[i]], 1.0f);
    if (i < N_) atomicAdd(&g_gcnt[g_batch[i]], 1);
}

__global__ void scan_ptr_kernel() {
    if (threadIdx.x != 0) return;
    int acc = 0;
    g_ptr[0] = 0;
    for (int b = 0; b < B_; b++) { acc += g_gcnt[b]; g_ptr[b + 1] = acc; }
}

// ---------------- fused encoders: in_linear + edge_hidden ----------------
__global__ void encoders_kernel(const float* __restrict__ x,
                                const float* __restrict__ W_in, const float* __restrict__ b_in,
                                const float* __restrict__ ea,
                                const float* __restrict__ W_e1, const float* __restrict__ b_e1) {
    int i = blockIdx.x * blockDim.x + threadIdx.x;
    if (i < N_ * D_) {
        int n = i >> 6, f = i & 63;
        float acc = b_in[f];
        const float* xr = x + n * ND_;
        const float* wr = W_in + f * ND_;
#pragma unroll
        for (int k = 0; k < ND_; k++) acc += xr[k] * wr[k];
        g_h[i] = fmaxf(acc, 0.f);
    } else if (i < N_ * D_ + E_ * D_) {
        int j = i - N_ * D_;
        int e = j >> 6, f = j & 63;
        float acc = b_e1[f];
        const float* er = ea + e * ED_;
        const float* wr = W_e1 + f * ED_;
#pragma unroll
        for (int k = 0; k < ED_; k++) acc += er[k] * wr[k];
        g_r[j] = fmaxf(acc, 0.f);
    }
}

// ============ ew GEMM via mma.sync bf16-split: g_ew = g_r @ W_e2^T + b_e2 ============
// C[E,4096] = A[E,64] @ B[64,4096]; B[k,c] = W_e2[c,k] (W rows are k-contiguous).
// CTA tile 128(M) x 64(N), K=64. 8 warps, each 32x32. bf16 hi/lo split, 3 products.
#define EWPAD 72     // bf16 row stride (144B): conflict-free ldmatrix phases
#define SM_AHI 0
#define SM_ALO (SM_AHI + 128 * EWPAD * 2)   // 18432
#define SM_BHI (SM_ALO + 128 * EWPAD * 2)   // 36864
#define SM_BLO (SM_BHI + 64 * EWPAD * 2)    // 46080
#define SM_TOTAL (SM_BLO + 64 * EWPAD * 2)  // 55296

__device__ __forceinline__ void split_pack2(float a, float b, uint32_t& hi, uint32_t& lo) {
    __nv_bfloat16 ah = __float2bfloat16(a), bh = __float2bfloat16(b);
    float ar = a - __bfloat162float(ah), br = b - __bfloat162float(bh);
    __nv_bfloat16 al = __float2bfloat16(ar), bl = __float2bfloat16(br);
    uint16_t ahu = *(uint16_t*)&ah, bhu = *(uint16_t*)&bh;
    uint16_t alu = *(uint16_t*)&al, blu = *(uint16_t*)&bl;
    hi = (uint32_t)ahu | ((uint32_t)bhu << 16);
    lo = (uint32_t)alu | ((uint32_t)blu << 16);
}

__device__ __forceinline__ void split_store_row(const float* src, bool valid,
                                                char* smem, int hi_off, int lo_off,
                                                uint32_t off) {
    float4 v0 = valid ? *(const float4*)(src) : make_float4(0, 0, 0, 0);
    float4 v1 = valid ? *(const float4*)(src + 4) : make_float4(0, 0, 0, 0);
    uint32_t h0, h1, h2, h3, l0, l1, l2, l3;
    split_pack2(v0.x, v0.y, h0, l0);
    split_pack2(v0.z, v0.w, h1, l1);
    split_pack2(v1.x, v1.y, h2, l2);
    split_pack2(v1.z, v1.w, h3, l3);
    *(uint4*)(smem + hi_off + off) = make_uint4(h0, h1, h2, h3);
    *(uint4*)(smem + lo_off + off) = make_uint4(l0, l1, l2, l3);
}

__device__ __forceinline__ void ldsm4(uint32_t addr, uint32_t* r) {
    asm volatile("ldmatrix.sync.aligned.m8n8.x4.shared.b16 {%0,%1,%2,%3}, [%4];"
                 : "=r"(r[0]), "=r"(r[1]), "=r"(r[2]), "=r"(r[3]) : "r"(addr));
}

__device__ __forceinline__ void mma_bf16(float* c, const uint32_t* a, uint32_t b0, uint32_t b1) {
    asm volatile(
        "mma.sync.aligned.m16n8k16.row.col.f32.bf16.bf16.f32 "
        "{%0,%1,%2,%3}, {%4,%5,%6,%7}, {%8,%9}, {%0,%1,%2,%3};"
        : "+f"(c[0]), "+f"(c[1]), "+f"(c[2]), "+f"(c[3])
        : "r"(a[0]), "r"(a[1]), "r"(a[2]), "r"(a[3]), "r"(b0), "r"(b1));
}

__global__ void __launch_bounds__(256) ew_mma_kernel(const float* __restrict__ W,
                                                     const float* __restrict__ bias) {
    extern __shared__ char smem[];
    int tid = threadIdx.x;
    int e0 = blockIdx.y * 128;
    int c0 = blockIdx.x * 64;

    // load A tile (128 edges x 64 k) split hi/lo
    for (int idx = tid; idx < 128 * 8; idx += 256) {
        int row = idx >> 3, k8 = idx & 7;
        int e = e0 + row;
        uint32_t off = (uint32_t)(row * EWPAD + k8 * 8) * 2;
        split_store_row(&g_r[e * 64 + k8 * 8], e < E_, smem, SM_AHI, SM_ALO, off);
    }
    // load B tile (64 cols x 64 k): row n = W_e2 row (c0+n), k-contiguous
    for (int idx = tid; idx < 64 * 8; idx += 256) {
        int row = idx >> 3, k8 = idx & 7;
        uint32_t off = (uint32_t)(row * EWPAD + k8 * 8) * 2;
        split_store_row(&W[(c0 + row) * 64 + k8 * 8], true, smem, SM_BHI, SM_BLO, off);
    }
    __syncthreads();

    int w = tid >> 5, lane = tid & 31;
    int wm = w & 3, wn = w >> 2;      // warp tile: rows wm*32, cols wn*32
    int r8 = lane & 7, q = lane >> 3;
    uint32_t sb = smem_u32(smem);

    // A ldmatrix quads: q0 rows0-7/k0, q1 rows8-15/k0, q2 rows0-7/k0+8, q3 rows8-15/k0+8
    int a_row = ((q & 1) ? 8 : 0) + r8;
    int a_col = (q >= 2) ? 8 : 0;
    // B quads: q0 n r/k0, q1 n r/k0+8, q2 n 8+r/k0, q3 n 8+r/k0+8
    int b_row = ((q >= 2) ? 8 : 0) + r8;
    int b_col = (q & 1) ? 8 : 0;

    float c[2][4][4];
#pragma unroll
    for (int t = 0; t < 2; t++)
#pragma unroll
        for (int n = 0; n < 4; n++)
#pragma unroll
            for (int j = 0; j < 4; j++) c[t][n][j] = 0.f;

#pragma unroll
    for (int k0 = 0; k0 < 64; k0 += 16) {
        uint32_t ahi[2][4], alo[2][4], bhi[2][4], blo[2][4];
#pragma unroll
        for (int t = 0; t < 2; t++) {
            uint32_t ad = sb + SM_AHI +
                (uint32_t)((wm * 32 + t * 16 + a_row) * EWPAD + k0 + a_col) * 2;
            ldsm4(ad, ahi[t]);
            ldsm4(ad + (SM_ALO - SM_AHI), alo[t]);
        }
#pragma unroll
        for (int p = 0; p < 2; p++) {
            uint32_t bd = sb + SM_BHI +
                (uint32_t)((wn * 32 + p * 16 + b_row) * EWPAD + k0 + b_col) * 2;
            ldsm4(bd, bhi[p]);
            ldsm4(bd + (SM_BLO - SM_BHI), blo[p]);
        }
#pragma unroll
        for (int t = 0; t < 2; t++)
#pragma unroll
            for (int n = 0; n < 4; n++) {
                int p = n >> 1, s = (n & 1) * 2;
                mma_bf16(c[t][n], ahi[t], bhi[p][s], bhi[p][s + 1]);
                mma_bf16(c[t][n], ahi[t], blo[p][s], blo[p][s + 1]);
                mma_bf16(c[t][n], alo[t], bhi[p][s], bhi[p][s + 1]);
            }
    }

    // epilogue: add bias, store fp32
    int g = lane >> 2, qq = lane & 3;
#pragma unroll
    for (int t = 0; t < 2; t++) {
        int row0 = e0 + wm * 32 + t * 16 + g;
#pragma unroll
        for (int n = 0; n < 4; n++) {
            int col = c0 + wn * 32 + n * 8 + qq * 2;
            float bb0 = __ldg(&bias[col]), bb1 = __ldg(&bias[col + 1]);
            if (row0 < E_) {
                float2 v = make_float2(c[t][n][0] + bb0, c[t][n][1] + bb1);
                *(float2*)&g_ew[(size_t)row0 * DD_ + col] = v;
            }
            if (row0 + 8 < E_) {
                float2 v = make_float2(c[t][n][2] + bb0, c[t][n][3] + bb1);
                *(float2*)&g_ew[(size_t)(row0 + 8) * DD_ + col] = v;
            }
        }
    }
}

// ---------------- message + scatter: agg[dst] += ew[e]^T h[src] ----------------
__global__ void msg_kernel(int it) {
    int sub = threadIdx.x >> 6;
    int f = threadIdx.x & 63;
    int e = blockIdx.x * 4 + sub;
    __shared__ float s[4][64];
    int valid = (e < E_);
    int srcn = 0, dstn = 0;
    if (valid) {
        srcn = g_src[e];
        dstn = g_dst[e];
        s[sub][f] = g_h[srcn * 64 + f];
    }
    __syncthreads();
    if (!valid) return;
    const float* w = &g_ew[(size_t)e * DD_ + f];
    const float* sv = s[sub];
    float acc = 0.f;
#pragma unroll
    for (int d = 0; d < 64; d++) acc += sv[d] * w[d * 64];
    atomicAdd(&g_agg[it * N_ * D_ + dstn * 64 + f], acc);
}

// ---------------- GRU update over node tiles of 16 ----------------
__global__ void __launch_bounds__(192) gru_kernel(const float* __restrict__ Wih,
                                                  const float* __restrict__ bih,
                                                  const float* __restrict__ Whh,
                                                  const float* __restrict__ bhh,
                                                  const float* __restrict__ bconv,
                                                  int it) {
    __shared__ float Msm[16][64];
    __shared__ float Hsm[16][64];
    __shared__ float GI[16][192];
    __shared__ float GH[16][192];
    int n0 = blockIdx.x * 16;
    int tid = threadIdx.x;
    const float* agg = &g_agg[it * N_ * D_];

    for (int idx = tid; idx < 16 * 64; idx += 192) {
        int m = idx >> 6, k = idx & 63;
        int n = n0 + m;
        if (n < N_) {
            float cdeg = fmaxf(g_cnt[n], 1.0f);
            Msm[m][k] = fmaxf(agg[n * 64 + k] / cdeg + bconv[k], 0.f);
            Hsm[m][k] = g_h[n * 64 + k];
        } else {
            Msm[m][k] = 0.f;
            Hsm[m][k] = 0.f;
        }
    }
    __syncthreads();

    float wih[64], whh[64];
    const float* wi = Wih + tid * 64;
    const float* wh = Whh + tid * 64;
#pragma unroll
    for (int k = 0; k < 64; k++) { wih[k] = __ldg(&wi[k]); whh[k] = __ldg(&wh[k]); }
    float bi = bih[tid], bh = bhh[tid];

#pragma unroll 4
    for (int m = 0; m < 16; m++) {
        float ai = bi, ah = bh;
#pragma unroll
        for (int k = 0; k < 64; k++) {
            ai += Msm[m][k] * wih[k];
            ah += Hsm[m][k] * whh[k];
        }
        GI[m][tid] = ai;
        GH[m][tid] = ah;
    }
    __syncthreads();

    for (int idx = tid; idx < 16 * 64; idx += 192) {
        int m = idx >> 6, f = idx & 63;
        int n = n0 + m;
        if (n >= N_) continue;
        float r = sigm(GI[m][f] + GH[m][f]);
        float z = sigm(GI[m][64 + f] + GH[m][64 + f]);
        float nn = tanhf(GI[m][128 + f] + r * GH[m][128 + f]);
        float hnew = (1.f - z) * nn + z * Hsm[m][f];
        g_h[n * 64 + f] = hnew;
    }
}

// ---------------- Set2Set LSTM cell (8 graphs per 256-thread block) ----------------
__global__ void lstm_kernel(const float* __restrict__ Wih, const float* __restrict__ bih,
                            const float* __restrict__ Whh, const float* __restrict__ bhh) {
    __shared__ float qs[8][128];
    __shared__ float hs[8][64];
    __shared__ float gsm[8][256];
    int b0 = blockIdx.x * 8;
    int tid = threadIdx.x;

    for (int idx = tid; idx < 8 * 128; idx += 256) {
        int g = idx >> 7, k = idx & 127;
        int b = b0 + g;
        qs[g][k] = (b < B_) ? g_qstar[b * 128 + k] : 0.f;
    }
    for (int idx = tid; idx < 8 * 64; idx += 256) {
        int g = idx >> 6, k = idx & 63;
        int b = b0 + g;
        hs[g][k] = (b < B_) ? g_hl[b * 64 + k] : 0.f;
    }
    __syncthreads();

    int j = tid;
    float acc[8];
    float bsum = bih[j] + bhh[j];
#pragma unroll
    for (int g = 0; g < 8; g++) acc[g] = bsum;
    const float* wi = Wih + j * 128;
    const float* wh = Whh + j * 64;
#pragma unroll 4
    for (int k = 0; k < 128; k++) {
        float w = __ldg(&wi[k]);
#pragma unroll
        for (int g = 0; g < 8; g++) acc[g] += qs[g][k] * w;
    }
#pragma unroll 4
    for (int k = 0; k < 64; k++) {
        float w = __ldg(&wh[k]);
#pragma unroll
        for (int g = 0; g < 8; g++) acc[g] += hs[g][k] * w;
    }
#pragma unroll
    for (int g = 0; g < 8; g++) gsm[g][j] = acc[g];
    __syncthreads();

    for (int idx = tid; idx < 8 * 64; idx += 256) {
        int g = idx >> 6, f = idx & 63;
        int b = b0 + g;
        if (b >= B_) continue;
        float ig = sigm(gsm[g][f]);
        float fg = sigm(gsm[g][64 + f]);
        float gg = tanhf(gsm[g][128 + f]);
        float og = sigm(gsm[g][192 + f]);
        float c = fg * g_cl[b * 64 + f] + ig * gg;
        float h = og * tanhf(c);
        g_cl[b * 64 + f] = c;
        g_hl[b * 64 + f] = h;
    }
}

// ---------------- attention (segment softmax + weighted sum) per graph ----------------
__global__ void attn_kernel() {
    int b = blockIdx.x;
    int tid = threadIdx.x;   // 128 threads
    __shared__ float qv[64];
    __shared__ float red[128];
    if (tid < 64) qv[tid] = g_hl[b * 64 + tid];
    __syncthreads();

    int s = g_ptr[b], eend = g_ptr[b + 1];

    float lmax = -INFINITY;
    for (int n = s + tid; n < eend; n += 128) {
        const float4* hr = (const float4*)&g_h[n * 64];
        const float4* qq = (const float4*)qv;
        float d = 0.f;
#pragma unroll
        for (int k = 0; k < 16; k++) {
            float4 a = hr[k], c = qq[k];
            d += a.x * c.x + a.y * c.y + a.z * c.z + a.w * c.w;
        }
        g_e[n] = d;
        lmax = fmaxf(lmax, d);
    }
    red[tid] = lmax;
    __syncthreads();
    for (int o = 64; o > 0; o >>= 1) {
        if (tid < o) red[tid] = fmaxf(red[tid], red[tid + o]);
        __syncthreads();
    }
    float mmax = red[0];
    __syncthreads();

    float lsum = 0.f;
    for (int n = s + tid; n < eend; n += 128) {
        float a = expf(g_e[n] - mmax);
        g_e[n] = a;
        lsum += a;
    }
    red[tid] = lsum;
    __syncthreads();
    for (int o = 64; o > 0; o >>= 1) {
        if (tid < o) red[tid] += red[tid + o];
        __syncthreads();
    }
    float den = red[0];
    __syncthreads();

    if (tid < 64) {
        float accr = 0.f;
        for (int n = s; n < eend; n++) accr += g_e[n] * g_h[n * 64 + tid];
        float rv = (den > 0.f) ? accr / den : 0.f;
        g_qstar[b * 128 + tid] = qv[tid];
        g_qstar[b * 128 + 64 + tid] = rv;
    }
}

// ---------------- output head ----------------
__global__ void out_head_kernel(const float* __restrict__ Wo1, const float* __restrict__ bo1,
                                const float* __restrict__ Wo2, const float* __restrict__ bo2,
                                float* __restrict__ out) {
    int b = blockIdx.x;
    int j = threadIdx.x;   // 64
    __shared__ float qs[128];
    __shared__ float hr[64];
    qs[j] = g_qstar[b * 128 + j];
    qs[64 + j] = g_qstar[b * 128 + 64 + j];
    __syncthreads();
    float acc = bo1[j];
    const float* wr = Wo1 + j * 128;
#pragma unroll 4
    for (int k = 0; k < 128; k++) acc += qs[k] * wr[k];
    acc = fmaxf(acc, 0.f) * Wo2[j];
    hr[j] = acc;
    __syncthreads();
    for (int o = 32; o > 0; o >>= 1) {
        if (j < o) hr[j] += hr[j + o];
        __syncthreads();
    }
    if (j == 0) out[b] = hr[0] + bo2[0];
}

// ---------------- host launch ----------------
extern "C" void kernel_launch(void* const* d_in, const int* in_sizes, int n_in,
                              void* d_out, int out_size) {
    const float* x      = (const float*)d_in[0];
    const float* eattr  = (const float*)d_in[1];
    const float* W_in   = (const float*)d_in[2];
    const float* b_in   = (const float*)d_in[3];
    const float* W_e1   = (const float*)d_in[4];
    const float* b_e1   = (const float*)d_in[5];
    const float* W_e2   = (const float*)d_in[6];
    const float* b_e2   = (const float*)d_in[7];
    const float* b_conv = (const float*)d_in[8];
    const float* W_ih   = (const float*)d_in[9];
    const float* b_ih   = (const float*)d_in[10];
    const float* W_hh   = (const float*)d_in[11];
    const float* b_hh   = (const float*)d_in[12];
    const float* W_ih_l = (const float*)d_in[13];
    const float* b_ih_l = (const float*)d_in[14];
    const float* W_hh_l = (const float*)d_in[15];
    const float* b_hh_l = (const float*)d_in[16];
    const float* W_o1   = (const float*)d_in[17];
    const float* b_o1   = (const float*)d_in[18];
    const float* W_o2   = (const float*)d_in[19];
    const float* b_o2   = (const float*)d_in[20];
    const void*  eidx   = d_in[21];
    const void*  batch  = d_in[22];
    float* out = (float*)d_out;

    static bool attr_set = false;
    if (!attr_set) {
        cudaFuncSetAttribute(ew_mma_kernel,
                             cudaFuncAttributeMaxDynamicSharedMemorySize, SM_TOTAL);
        attr_set = true;
    }

    // preprocessing
    detect_kernel<<<1, 32>>>(eidx, batch);
    convert_kernel<<<(E_ + 255) / 256, 256>>>(eidx, batch);
    init_zero_kernel<<<(3 * N_ * D_ + 255) / 256, 256>>>();
    counts_kernel<<<(E_ + 255) / 256, 256>>>();
    scan_ptr_kernel<<<1, 32>>>();

    // encoders (fused)
    encoders_kernel<<<((N_ + E_) * D_ + 255) / 256, 256>>>(x, W_in, b_in, eattr, W_e1, b_e1);

    // edge-conditioned weight tensor via mma.sync bf16-split
    dim3 ggrid(DD_ / 64, (E_ + 127) / 128);
    ew_mma_kernel<<<ggrid, 256, SM_TOTAL>>>(W_e2, b_e2);

    // 3 message-passing + GRU iterations (agg buffers pre-zeroed)
    for (int it = 0; it < 3; it++) {
        msg_kernel<<<(E_ + 3) / 4, 256>>>(it);
        gru_kernel<<<(N_ + 15) / 16, 192>>>(W_ih, b_ih, W_hh, b_hh, b_conv, it);
    }

    // Set2Set (q_star/hl/cl pre-zeroed)
    for (int it = 0; it < 3; it++) {
        lstm_kernel<<<(B_ + 7) / 8, 256>>>(W_ih_l, b_ih_l, W_hh_l, b_hh_l);
        attn_kernel<<<B_, 128>>>();
    }

    out_head_kernel<<<B_, 64>>>(W_o1, b_o1, W_o2, b_o2, out);
}